// round 10
// baseline (speedup 1.0000x reference)
#include <cuda_runtime.h>
#include <math.h>
#include <stdint.h>

// out[b] = W_cls * prod_q cos^2( (tanh(x_b . w_q + b_q) - tanh(ref_q)) / 2 ) + b_cls
// Product-state overlap factorizes per qubit; overlap is real, so the
// "quantum" pipeline reduces to a [B,1024]x[1024,4] projection + a few
// transcendentals per row.
//
// FINAL config (proven across R6/R8/R9, 47.58-47.87us = floor +- noise):
//  - persistent CTAs, grid = SMs*4 (equal residency on all 152 SMs)
//  - cp.async double-buffered smem staging (in-flight bytes live in SMEM)
//  - cross-block pipeline; empty commit_group wrap keeps FIFO accounting
//  - R10 micro: prefetch issued right after the stage-buffer read, before
//    the FMA block (buffer already copied to registers -> safe)
//
// Measured floor: 268.4 MB mandatory read / ~5.6 TB/s achievable ~= 47.6 us.

#define THREADS 256
#define WARPS   8
#define D       1024
#define DV      256
#define CHUNKS  8
#define ROWS    4
#define RPB     (WARPS * ROWS)   // 32 rows per block-iter

__device__ __forceinline__ void cp_async16(uint32_t dst_smem, const void* src) {
    asm volatile("cp.async.cg.shared.global [%0], [%1], 16;\n"
                 :: "r"(dst_smem), "l"(src) : "memory");
}
__device__ __forceinline__ void cp_commit() {
    asm volatile("cp.async.commit_group;\n" ::: "memory");
}
template <int N>
__device__ __forceinline__ void cp_wait() {
    asm volatile("cp.async.wait_group %0;\n" :: "n"(N) : "memory");
}

__global__ __launch_bounds__(THREADS, 4)
void qkc_kernel(const float* __restrict__ features,
                const float* __restrict__ W_proj,
                const float* __restrict__ b_proj,
                const float* __restrict__ ref_vec,
                const float* __restrict__ W_cls,
                const float* __restrict__ b_cls,
                float* __restrict__ out,
                int B)
{
    __shared__ float4 ws[4][DV];                     // 16 KB
    __shared__ float4 stage[WARPS][2][ROWS][32];     // 32 KB

    const float4* Wv = reinterpret_cast<const float4*>(W_proj);
    #pragma unroll
    for (int i = threadIdx.x; i < 4 * DV; i += THREADS)
        ws[i >> 8][i & (DV - 1)] = Wv[i];
    __syncthreads();

    const int warp = threadIdx.x >> 5;
    const int lane = threadIdx.x & 31;
    const int NB = B / RPB;
    const int stride = gridDim.x;

    const float4* __restrict__ xbase = reinterpret_cast<const float4*>(features);

    uint32_t sbuf[2][ROWS];
    #pragma unroll
    for (int s = 0; s < 2; ++s)
        #pragma unroll
        for (int r = 0; r < ROWS; ++r)
            sbuf[s][r] = (uint32_t)__cvta_generic_to_shared(&stage[warp][s][r][lane]);

    int rb = blockIdx.x;
    if (rb >= NB) return;

    const float4* ptr_cur = xbase + (size_t)(rb * RPB + warp * ROWS) * DV + lane;

    // Prime the pipe: chunks 0,1 of the first block
    #pragma unroll
    for (int r = 0; r < ROWS; ++r) cp_async16(sbuf[0][r], ptr_cur + (size_t)r * DV);
    cp_commit();
    #pragma unroll
    for (int r = 0; r < ROWS; ++r) cp_async16(sbuf[1][r], ptr_cur + (size_t)r * DV + 32);
    cp_commit();

    for (; rb < NB; rb += stride) {
        const bool has_next = (rb + stride < NB);
        const float4* ptr_next =
            xbase + (size_t)((size_t)(rb + stride) * RPB + warp * ROWS) * DV + lane;

        float acc[ROWS][4];
        #pragma unroll
        for (int r = 0; r < ROWS; ++r)
            #pragma unroll
            for (int q = 0; q < 4; ++q)
                acc[r][q] = 0.f;

        #pragma unroll
        for (int c = 0; c < CHUNKS; ++c) {
            cp_wait<1>();   // chunk c's group complete (FIFO, <=1 younger pending)

            // Pull chunk c into registers first...
            float4 xr[ROWS];
            #pragma unroll
            for (int r = 0; r < ROWS; ++r)
                xr[r] = stage[warp][c & 1][r][lane];

            // ...then immediately refill the freed buffer with chunk c+2
            // (before the FMA block: prefetch starts ~16 issue slots earlier).
            // On the final iteration the wrap groups are EMPTY commits.
            if (c < CHUNKS - 2) {
                #pragma unroll
                for (int r = 0; r < ROWS; ++r)
                    cp_async16(sbuf[c & 1][r], ptr_cur + (size_t)r * DV + 32 * (c + 2));
            } else if (has_next) {
                #pragma unroll
                for (int r = 0; r < ROWS; ++r)
                    cp_async16(sbuf[c & 1][r],
                               ptr_next + (size_t)r * DV + 32 * (c - (CHUNKS - 2)));
            }
            cp_commit();

            const int p = lane + 32 * c;
            #pragma unroll
            for (int q = 0; q < 4; ++q) {
                float4 w = ws[q][p];
                #pragma unroll
                for (int r = 0; r < ROWS; ++r)
                    acc[r][q] += xr[r].x * w.x + xr[r].y * w.y
                               + xr[r].z * w.z + xr[r].w * w.w;
            }
        }

        // Full butterfly reduction; overlaps the two in-flight prefetch
        // groups of the next block.
        #pragma unroll
        for (int r = 0; r < ROWS; ++r)
            #pragma unroll
            for (int q = 0; q < 4; ++q)
                #pragma unroll
                for (int o = 16; o > 0; o >>= 1)
                    acc[r][q] += __shfl_xor_sync(0xFFFFFFFFu, acc[r][q], o);

        if (lane < ROWS) {
            float fid = 1.0f;
            #pragma unroll
            for (int q = 0; q < 4; ++q) {
                float v = (lane == 0) ? acc[0][q]
                        : (lane == 1) ? acc[1][q]
                        : (lane == 2) ? acc[2][q]
                        :               acc[3][q];
                float t  = tanhf(v + b_proj[q]);
                float rr = tanhf(ref_vec[q]);
                float cd = cosf((t - rr) * 0.5f);
                fid *= cd * cd;
            }
            out[rb * RPB + warp * ROWS + lane] = fid * W_cls[0] + b_cls[0];
        }

        ptr_cur = ptr_next;
    }

    cp_wait<0>();   // drain (empty) groups before exit
}

extern "C" void kernel_launch(void* const* d_in, const int* in_sizes, int n_in,
                              void* d_out, int out_size)
{
    const float* features = (const float*)d_in[0];
    const float* W_proj   = (const float*)d_in[1];
    const float* b_proj   = (const float*)d_in[2];
    const float* ref_vec  = (const float*)d_in[3];
    const float* W_cls    = (const float*)d_in[4];
    const float* b_cls    = (const float*)d_in[5];
    float* out = (float*)d_out;

    const int B  = in_sizes[0] / D;   // 65536
    const int NB = B / RPB;           // 2048

    static int sms = 0;
    if (sms == 0) cudaDeviceGetAttribute(&sms, cudaDevAttrMultiProcessorCount, 0);
    int grid = sms * 4;               // equal resident CTAs on every SM
    if (grid > NB) grid = NB;

    qkc_kernel<<<grid, THREADS>>>(features, W_proj, b_proj, ref_vec,
                                  W_cls, b_cls, out, B);
}

// round 11
// speedup vs baseline: 1.0410x; 1.0410x over previous
#include <cuda_runtime.h>
#include <math.h>
#include <stdint.h>

// out[b] = W_cls * prod_q cos^2( (tanh(x_b . w_q + b_q) - tanh(ref_q)) / 2 ) + b_cls
// Product-state overlap factorizes per qubit; overlap is real.
//
// FINAL = exact R6 (measured best: 47.58us; R8/R9 replicas 47.87us).
// cp.async smem staging, persistent CTAs (grid = SMs*4, equal residency),
// cross-block pipeline, full butterfly reduction, empty-commit wrap.
// Ordering matters: consume stage buffer -> FMA block -> issue prefetch
// (R10's prefetch-before-FMA reorder regressed to 49.5us).
//
// Floor: 268.4 MB mandatory fp32 read / ~5.6 TB/s achievable ~= 47.6 us.

#define THREADS 256
#define WARPS   8
#define D       1024
#define DV      256
#define CHUNKS  8
#define ROWS    4
#define RPB     (WARPS * ROWS)   // 32 rows per block-iter

__device__ __forceinline__ void cp_async16(uint32_t dst_smem, const void* src) {
    asm volatile("cp.async.cg.shared.global [%0], [%1], 16;\n"
                 :: "r"(dst_smem), "l"(src) : "memory");
}
__device__ __forceinline__ void cp_commit() {
    asm volatile("cp.async.commit_group;\n" ::: "memory");
}
template <int N>
__device__ __forceinline__ void cp_wait() {
    asm volatile("cp.async.wait_group %0;\n" :: "n"(N) : "memory");
}

__global__ __launch_bounds__(THREADS, 4)
void qkc_kernel(const float* __restrict__ features,
                const float* __restrict__ W_proj,
                const float* __restrict__ b_proj,
                const float* __restrict__ ref_vec,
                const float* __restrict__ W_cls,
                const float* __restrict__ b_cls,
                float* __restrict__ out,
                int B)
{
    __shared__ float4 ws[4][DV];                     // 16 KB
    __shared__ float4 stage[WARPS][2][ROWS][32];     // 32 KB

    const float4* Wv = reinterpret_cast<const float4*>(W_proj);
    #pragma unroll
    for (int i = threadIdx.x; i < 4 * DV; i += THREADS)
        ws[i >> 8][i & (DV - 1)] = Wv[i];
    __syncthreads();

    const int warp = threadIdx.x >> 5;
    const int lane = threadIdx.x & 31;
    const int NB = B / RPB;
    const int stride = gridDim.x;

    const float4* __restrict__ xbase = reinterpret_cast<const float4*>(features);

    uint32_t sbuf[2][ROWS];
    #pragma unroll
    for (int s = 0; s < 2; ++s)
        #pragma unroll
        for (int r = 0; r < ROWS; ++r)
            sbuf[s][r] = (uint32_t)__cvta_generic_to_shared(&stage[warp][s][r][lane]);

    int rb = blockIdx.x;
    if (rb >= NB) return;

    const float4* ptr_cur = xbase + (size_t)(rb * RPB + warp * ROWS) * DV + lane;

    // Prime the pipe: chunks 0,1 of the first block
    #pragma unroll
    for (int r = 0; r < ROWS; ++r) cp_async16(sbuf[0][r], ptr_cur + (size_t)r * DV);
    cp_commit();
    #pragma unroll
    for (int r = 0; r < ROWS; ++r) cp_async16(sbuf[1][r], ptr_cur + (size_t)r * DV + 32);
    cp_commit();

    for (; rb < NB; rb += stride) {
        const bool has_next = (rb + stride < NB);
        const float4* ptr_next =
            xbase + (size_t)((size_t)(rb + stride) * RPB + warp * ROWS) * DV + lane;

        float acc[ROWS][4];
        #pragma unroll
        for (int r = 0; r < ROWS; ++r)
            #pragma unroll
            for (int q = 0; q < 4; ++q)
                acc[r][q] = 0.f;

        #pragma unroll
        for (int c = 0; c < CHUNKS; ++c) {
            cp_wait<1>();   // chunk c's group complete (FIFO, <=1 younger pending)

            float4 xr[ROWS];
            #pragma unroll
            for (int r = 0; r < ROWS; ++r)
                xr[r] = stage[warp][c & 1][r][lane];

            const int p = lane + 32 * c;
            #pragma unroll
            for (int q = 0; q < 4; ++q) {
                float4 w = ws[q][p];
                #pragma unroll
                for (int r = 0; r < ROWS; ++r)
                    acc[r][q] += xr[r].x * w.x + xr[r].y * w.y
                               + xr[r].z * w.z + xr[r].w * w.w;
            }

            // Issue chunk c+2 of the stream; on the final iteration the two
            // wrap groups are EMPTY commits (FIFO accounting intact, no reads).
            if (c < CHUNKS - 2) {
                #pragma unroll
                for (int r = 0; r < ROWS; ++r)
                    cp_async16(sbuf[c & 1][r], ptr_cur + (size_t)r * DV + 32 * (c + 2));
            } else if (has_next) {
                #pragma unroll
                for (int r = 0; r < ROWS; ++r)
                    cp_async16(sbuf[c & 1][r],
                               ptr_next + (size_t)r * DV + 32 * (c - (CHUNKS - 2)));
            }
            cp_commit();
        }

        // Full butterfly reduction. Overlaps the two in-flight prefetch
        // groups of the next block.
        #pragma unroll
        for (int r = 0; r < ROWS; ++r)
            #pragma unroll
            for (int q = 0; q < 4; ++q)
                #pragma unroll
                for (int o = 16; o > 0; o >>= 1)
                    acc[r][q] += __shfl_xor_sync(0xFFFFFFFFu, acc[r][q], o);

        if (lane < ROWS) {
            float fid = 1.0f;
            #pragma unroll
            for (int q = 0; q < 4; ++q) {
                float v = (lane == 0) ? acc[0][q]
                        : (lane == 1) ? acc[1][q]
                        : (lane == 2) ? acc[2][q]
                        :               acc[3][q];
                float t  = tanhf(v + b_proj[q]);
                float rr = tanhf(ref_vec[q]);
                float cd = cosf((t - rr) * 0.5f);
                fid *= cd * cd;
            }
            out[rb * RPB + warp * ROWS + lane] = fid * W_cls[0] + b_cls[0];
        }

        ptr_cur = ptr_next;
    }

    cp_wait<0>();   // drain (empty) groups before exit
}

extern "C" void kernel_launch(void* const* d_in, const int* in_sizes, int n_in,
                              void* d_out, int out_size)
{
    const float* features = (const float*)d_in[0];
    const float* W_proj   = (const float*)d_in[1];
    const float* b_proj   = (const float*)d_in[2];
    const float* ref_vec  = (const float*)d_in[3];
    const float* W_cls    = (const float*)d_in[4];
    const float* b_cls    = (const float*)d_in[5];
    float* out = (float*)d_out;

    const int B  = in_sizes[0] / D;   // 65536
    const int NB = B / RPB;           // 2048

    static int sms = 0;
    if (sms == 0) cudaDeviceGetAttribute(&sms, cudaDevAttrMultiProcessorCount, 0);
    int grid = sms * 4;               // equal resident CTAs on every SM
    if (grid > NB) grid = NB;

    qkc_kernel<<<grid, THREADS>>>(features, W_proj, b_proj, ref_vec,
                                  W_cls, b_cls, out, B);
}